// round 1
// baseline (speedup 1.0000x reference)
#include <cuda_runtime.h>
#include <float.h>

#define N_REF   500000
#define N_PC    128
#define N_FEAT  2000
#define TOP_K   16

#define BLOCKS           296
#define THREADS          256
#define WARPS_PER_BLOCK  (THREADS / 32)
#define TOTAL_WARPS      (BLOCKS * WARPS_PER_BLOCK)   // 2368
#define N_CAND           (TOTAL_WARPS * TOP_K)        // 37888

#define PROJ_BLOCKS      50
#define FEAT_PER_BLOCK   (N_FEAT / PROJ_BLOCKS)       // 40

// Scratch (no cudaMalloc allowed)
__device__ float g_qpart[PROJ_BLOCKS * N_PC];
__device__ float g_query[N_PC];
__device__ float g_cand_d[N_CAND];
__device__ int   g_cand_i[N_CAND];

// ---------------------------------------------------------------------------
// Kernel A1: partial projection. Block b handles features [b*40, (b+1)*40).
// ---------------------------------------------------------------------------
__global__ void project_partial(const float* __restrict__ data_in,
                                const float* __restrict__ tmat) {
    int j  = threadIdx.x;          // 0..127 (PC index)
    int b  = blockIdx.x;
    int k0 = b * FEAT_PER_BLOCK;
    float acc = 0.0f;
    #pragma unroll 8
    for (int k = k0; k < k0 + FEAT_PER_BLOCK; k++) {
        acc += data_in[k] * tmat[k * N_PC + j];   // coalesced over j
    }
    g_qpart[b * N_PC + j] = acc;
}

// ---------------------------------------------------------------------------
// Kernel A2: reduce partials -> g_query[128]
// ---------------------------------------------------------------------------
__global__ void project_reduce() {
    int j = threadIdx.x;
    float acc = 0.0f;
    #pragma unroll
    for (int b = 0; b < PROJ_BLOCKS; b++) acc += g_qpart[b * N_PC + j];
    g_query[j] = acc;
}

// ---------------------------------------------------------------------------
// top-k insertion into a lane-private sorted (ascending) list of size 16.
// Dynamic indexing -> local memory, but it's touched ~40x per warp total.
// ---------------------------------------------------------------------------
__device__ __forceinline__ void topk_insert(float* d, int* ix, float v, int id) {
    int p = TOP_K - 1;
    #pragma unroll 1
    while (p > 0 && d[p - 1] > v) {
        d[p]  = d[p - 1];
        ix[p] = ix[p - 1];
        p--;
    }
    d[p]  = v;
    ix[p] = id;
}

// ---------------------------------------------------------------------------
// Kernel B: streaming L1 distance + per-warp top-16.
// One warp per row; lane l reads elements [4l, 4l+3] as float4 (512B/row,
// perfectly coalesced). Unroll 4 rows -> per-lane MLP=4 to saturate HBM.
// ---------------------------------------------------------------------------
__global__ void __launch_bounds__(THREADS, 2)
dist_topk_kernel(const float* __restrict__ ref) {
    const int lane = threadIdx.x & 31;
    const int gw   = blockIdx.x * WARPS_PER_BLOCK + (threadIdx.x >> 5);

    // query slice for this lane (constant across the whole loop)
    const float4 q = reinterpret_cast<const float4*>(g_query)[lane];

    const int chunk = (N_REF + TOTAL_WARPS - 1) / TOTAL_WARPS;  // 212
    int start = gw * chunk;
    int end   = start + chunk;
    if (start > N_REF) start = N_REF;
    if (end   > N_REF) end   = N_REF;

    float topd[TOP_K];
    int   topi[TOP_K];
    #pragma unroll
    for (int t = 0; t < TOP_K; t++) { topd[t] = FLT_MAX; topi[t] = 0; }
    float kmax = FLT_MAX;   // = topd[15], kept in a register (lane 0 only)

    const float4* __restrict__ ref4 = reinterpret_cast<const float4*>(ref);

    int r = start;
    for (; r + 4 <= end; r += 4) {
        // 4 independent streaming loads per lane (MLP=4, bypass-ish L2 reuse)
        float4 a0 = __ldcs(ref4 + (size_t)(r + 0) * (N_PC / 4) + lane);
        float4 a1 = __ldcs(ref4 + (size_t)(r + 1) * (N_PC / 4) + lane);
        float4 a2 = __ldcs(ref4 + (size_t)(r + 2) * (N_PC / 4) + lane);
        float4 a3 = __ldcs(ref4 + (size_t)(r + 3) * (N_PC / 4) + lane);

        float s0 = fabsf(a0.x - q.x) + fabsf(a0.y - q.y) + fabsf(a0.z - q.z) + fabsf(a0.w - q.w);
        float s1 = fabsf(a1.x - q.x) + fabsf(a1.y - q.y) + fabsf(a1.z - q.z) + fabsf(a1.w - q.w);
        float s2 = fabsf(a2.x - q.x) + fabsf(a2.y - q.y) + fabsf(a2.z - q.z) + fabsf(a2.w - q.w);
        float s3 = fabsf(a3.x - q.x) + fabsf(a3.y - q.y) + fabsf(a3.z - q.z) + fabsf(a3.w - q.w);

        #pragma unroll
        for (int off = 16; off > 0; off >>= 1) {
            s0 += __shfl_xor_sync(0xFFFFFFFFu, s0, off);
            s1 += __shfl_xor_sync(0xFFFFFFFFu, s1, off);
            s2 += __shfl_xor_sync(0xFFFFFFFFu, s2, off);
            s3 += __shfl_xor_sync(0xFFFFFFFFu, s3, off);
        }

        if (lane == 0) {
            if (s0 < kmax) { topk_insert(topd, topi, s0, r + 0); kmax = topd[TOP_K - 1]; }
            if (s1 < kmax) { topk_insert(topd, topi, s1, r + 1); kmax = topd[TOP_K - 1]; }
            if (s2 < kmax) { topk_insert(topd, topi, s2, r + 2); kmax = topd[TOP_K - 1]; }
            if (s3 < kmax) { topk_insert(topd, topi, s3, r + 3); kmax = topd[TOP_K - 1]; }
        }
    }
    // tail
    for (; r < end; r++) {
        float4 a0 = __ldcs(ref4 + (size_t)r * (N_PC / 4) + lane);
        float s0 = fabsf(a0.x - q.x) + fabsf(a0.y - q.y) + fabsf(a0.z - q.z) + fabsf(a0.w - q.w);
        #pragma unroll
        for (int off = 16; off > 0; off >>= 1)
            s0 += __shfl_xor_sync(0xFFFFFFFFu, s0, off);
        if (lane == 0 && s0 < kmax) {
            topk_insert(topd, topi, s0, r);
            kmax = topd[TOP_K - 1];
        }
    }

    if (lane == 0) {
        #pragma unroll
        for (int t = 0; t < TOP_K; t++) {
            g_cand_d[gw * TOP_K + t] = topd[t];
            g_cand_i[gw * TOP_K + t] = topi[t];
        }
    }
}

// ---------------------------------------------------------------------------
// Kernel C: merge 37888 candidates -> global top-16 -> mean(psuedo[idx]).
// Stage 1: each of 256 threads keeps a local top-16 over a strided slice.
// Stage 2: 4096 survivors in shared; 16 argmin passes with marking.
// ---------------------------------------------------------------------------
__global__ void merge_kernel(const float* __restrict__ psuedo,
                             float* __restrict__ out) {
    const int T   = 256;
    const int tid = threadIdx.x;

    __shared__ float s_cd[T * TOP_K];
    __shared__ int   s_ci[T * TOP_K];
    __shared__ float s_rd[T];
    __shared__ int   s_rp[T];

    float ld[TOP_K];
    int   li[TOP_K];
    #pragma unroll
    for (int t = 0; t < TOP_K; t++) { ld[t] = FLT_MAX; li[t] = 0; }
    float kmax = FLT_MAX;

    for (int c = tid; c < N_CAND; c += T) {
        float v = g_cand_d[c];
        if (v < kmax) {
            topk_insert(ld, li, v, g_cand_i[c]);
            kmax = ld[TOP_K - 1];
        }
    }
    #pragma unroll
    for (int t = 0; t < TOP_K; t++) {
        s_cd[tid * TOP_K + t] = ld[t];
        s_ci[tid * TOP_K + t] = li[t];
    }
    __syncthreads();

    float sum = 0.0f;
    for (int k = 0; k < TOP_K; k++) {
        float mind = FLT_MAX;
        int   minp = 0;
        #pragma unroll
        for (int t = 0; t < TOP_K; t++) {
            float v = s_cd[tid * TOP_K + t];
            if (v < mind) { mind = v; minp = tid * TOP_K + t; }
        }
        s_rd[tid] = mind;
        s_rp[tid] = minp;
        __syncthreads();
        for (int off = T / 2; off > 0; off >>= 1) {
            if (tid < off) {
                if (s_rd[tid + off] < s_rd[tid]) {
                    s_rd[tid] = s_rd[tid + off];
                    s_rp[tid] = s_rp[tid + off];
                }
            }
            __syncthreads();
        }
        if (tid == 0) {
            int p = s_rp[0];
            sum += psuedo[s_ci[p]];
            s_cd[p] = FLT_MAX;   // exclude picked candidate
        }
        __syncthreads();
    }

    if (tid == 0) out[0] = sum * (1.0f / TOP_K);
}

// ---------------------------------------------------------------------------
// Launch. Inputs per metadata order: data_in, transform_mat, ref_data,
// psuedo, K (K hardcoded as TOP_K=16).
// ---------------------------------------------------------------------------
extern "C" void kernel_launch(void* const* d_in, const int* in_sizes, int n_in,
                              void* d_out, int out_size) {
    const float* data_in = (const float*)d_in[0];
    const float* tmat    = (const float*)d_in[1];
    const float* ref     = (const float*)d_in[2];
    const float* psuedo  = (const float*)d_in[3];
    float* out = (float*)d_out;

    project_partial<<<PROJ_BLOCKS, N_PC>>>(data_in, tmat);
    project_reduce<<<1, N_PC>>>();
    dist_topk_kernel<<<BLOCKS, THREADS>>>(ref);
    merge_kernel<<<1, 256>>>(psuedo, out);
}

// round 2
// speedup vs baseline: 4.0739x; 4.0739x over previous
#include <cuda_runtime.h>
#include <float.h>

#define N_REF   500000
#define N_PC    128
#define N_FEAT  2000
#define TOP_K   16

#define BLOCKS           592
#define THREADS          256
#define WARPS_PER_BLOCK  (THREADS / 32)
#define TOTAL_WARPS      (BLOCKS * WARPS_PER_BLOCK)   // 4736
#define N_CAND           (TOTAL_WARPS * TOP_K)        // 75776

#define PROJ_BLOCKS      50
#define FEAT_PER_BLOCK   (N_FEAT / PROJ_BLOCKS)       // 40

// Scratch (no cudaMalloc allowed)
__device__ float g_qpart[PROJ_BLOCKS * N_PC];
__device__ float g_query[N_PC];
__device__ float g_cand_d[N_CAND];
__device__ int   g_cand_i[N_CAND];

// ---------------------------------------------------------------------------
// Branch-free register-resident top-16 insert. d[] ascending; v bubbles in,
// previous max bubbles out. Fully unrolled -> pure FSETP/SEL, NO local memory.
// ---------------------------------------------------------------------------
__device__ __forceinline__ void bubble_insert(float (&d)[TOP_K], int (&ix)[TOP_K],
                                              float v, int id) {
    #pragma unroll
    for (int t = 0; t < TOP_K; t++) {
        bool sw  = v < d[t];
        float tv = d[t];
        int   ti = ix[t];
        d[t]  = sw ? v  : tv;
        ix[t] = sw ? id : ti;
        v     = sw ? tv : v;
        id    = sw ? ti : id;
    }
}

// Unrolled dynamic read of a 16-register array (SELs, no local memory)
__device__ __forceinline__ float get16f(const float (&a)[TOP_K], int p) {
    float r = a[0];
    #pragma unroll
    for (int t = 1; t < TOP_K; t++) r = (p == t) ? a[t] : r;
    return r;
}
__device__ __forceinline__ int get16i(const int (&a)[TOP_K], int p) {
    int r = a[0];
    #pragma unroll
    for (int t = 1; t < TOP_K; t++) r = (p == t) ? a[t] : r;
    return r;
}

// ---------------------------------------------------------------------------
// Kernel A1: partial projection. Block b handles features [b*40, (b+1)*40).
// ---------------------------------------------------------------------------
__global__ void project_partial(const float* __restrict__ data_in,
                                const float* __restrict__ tmat) {
    int j  = threadIdx.x;          // 0..127 (PC index)
    int b  = blockIdx.x;
    int k0 = b * FEAT_PER_BLOCK;
    float acc = 0.0f;
    #pragma unroll 8
    for (int k = k0; k < k0 + FEAT_PER_BLOCK; k++) {
        acc += data_in[k] * tmat[k * N_PC + j];   // coalesced over j
    }
    g_qpart[b * N_PC + j] = acc;
}

// ---------------------------------------------------------------------------
// Kernel A2: reduce partials -> g_query[128]
// ---------------------------------------------------------------------------
__global__ void project_reduce() {
    int j = threadIdx.x;
    float acc = 0.0f;
    #pragma unroll
    for (int b = 0; b < PROJ_BLOCKS; b++) acc += g_qpart[b * N_PC + j];
    g_query[j] = acc;
}

// ---------------------------------------------------------------------------
// Kernel B: streaming L1 distance + per-warp top-16.
// One warp per row; lane l reads a float4 (512B/row, perfectly coalesced).
// Unroll 4 rows -> per-lane MLP=4 to saturate HBM.
// ---------------------------------------------------------------------------
__global__ void __launch_bounds__(THREADS)
dist_topk_kernel(const float* __restrict__ ref) {
    const int lane = threadIdx.x & 31;
    const int gw   = blockIdx.x * WARPS_PER_BLOCK + (threadIdx.x >> 5);

    const float4 q = reinterpret_cast<const float4*>(g_query)[lane];

    const int chunk = (N_REF + TOTAL_WARPS - 1) / TOTAL_WARPS;  // 106
    int start = gw * chunk;
    int end   = start + chunk;
    if (start > N_REF) start = N_REF;
    if (end   > N_REF) end   = N_REF;

    float topd[TOP_K];
    int   topi[TOP_K];
    #pragma unroll
    for (int t = 0; t < TOP_K; t++) { topd[t] = FLT_MAX; topi[t] = 0; }
    float kmax = FLT_MAX;   // = topd[15] (meaningful at lane 0)

    const float4* __restrict__ ref4 = reinterpret_cast<const float4*>(ref);

    int r = start;
    for (; r + 4 <= end; r += 4) {
        float4 a0 = __ldcs(ref4 + (size_t)(r + 0) * (N_PC / 4) + lane);
        float4 a1 = __ldcs(ref4 + (size_t)(r + 1) * (N_PC / 4) + lane);
        float4 a2 = __ldcs(ref4 + (size_t)(r + 2) * (N_PC / 4) + lane);
        float4 a3 = __ldcs(ref4 + (size_t)(r + 3) * (N_PC / 4) + lane);

        float s0 = fabsf(a0.x - q.x) + fabsf(a0.y - q.y) + fabsf(a0.z - q.z) + fabsf(a0.w - q.w);
        float s1 = fabsf(a1.x - q.x) + fabsf(a1.y - q.y) + fabsf(a1.z - q.z) + fabsf(a1.w - q.w);
        float s2 = fabsf(a2.x - q.x) + fabsf(a2.y - q.y) + fabsf(a2.z - q.z) + fabsf(a2.w - q.w);
        float s3 = fabsf(a3.x - q.x) + fabsf(a3.y - q.y) + fabsf(a3.z - q.z) + fabsf(a3.w - q.w);

        #pragma unroll
        for (int off = 16; off > 0; off >>= 1) {
            s0 += __shfl_xor_sync(0xFFFFFFFFu, s0, off);
            s1 += __shfl_xor_sync(0xFFFFFFFFu, s1, off);
            s2 += __shfl_xor_sync(0xFFFFFFFFu, s2, off);
            s3 += __shfl_xor_sync(0xFFFFFFFFu, s3, off);
        }

        if (lane == 0) {
            if (s0 < kmax) { bubble_insert(topd, topi, s0, r + 0); kmax = topd[TOP_K - 1]; }
            if (s1 < kmax) { bubble_insert(topd, topi, s1, r + 1); kmax = topd[TOP_K - 1]; }
            if (s2 < kmax) { bubble_insert(topd, topi, s2, r + 2); kmax = topd[TOP_K - 1]; }
            if (s3 < kmax) { bubble_insert(topd, topi, s3, r + 3); kmax = topd[TOP_K - 1]; }
        }
    }
    for (; r < end; r++) {
        float4 a0 = __ldcs(ref4 + (size_t)r * (N_PC / 4) + lane);
        float s0 = fabsf(a0.x - q.x) + fabsf(a0.y - q.y) + fabsf(a0.z - q.z) + fabsf(a0.w - q.w);
        #pragma unroll
        for (int off = 16; off > 0; off >>= 1)
            s0 += __shfl_xor_sync(0xFFFFFFFFu, s0, off);
        if (lane == 0 && s0 < kmax) {
            bubble_insert(topd, topi, s0, r);
            kmax = topd[TOP_K - 1];
        }
    }

    if (lane == 0) {
        #pragma unroll
        for (int t = 0; t < TOP_K; t++) {
            g_cand_d[gw * TOP_K + t] = topd[t];
            g_cand_i[gw * TOP_K + t] = topi[t];
        }
    }
}

// ---------------------------------------------------------------------------
// Kernel C: merge candidates -> global top-16 -> mean(psuedo[idx]).
// Stage A: 256 threads, register top-16 over strided slices -> shared (4096).
// Stage B: warp 0, per-lane register top-16 over 128 shared entries.
// Stage C: 16 warp-shuffle argmin extraction rounds; lanes 0..15 hold the
//          winners; parallel psuedo gather; shuffle sum.
// ---------------------------------------------------------------------------
__global__ void merge_kernel(const float* __restrict__ psuedo,
                             float* __restrict__ out) {
    const int T    = 256;
    const int tid  = threadIdx.x;
    const int lane = tid & 31;

    __shared__ float s_d[T * TOP_K];   // 4096 floats
    __shared__ int   s_i[T * TOP_K];

    // ---- Stage A ----
    float d[TOP_K]; int ix[TOP_K];
    #pragma unroll
    for (int t = 0; t < TOP_K; t++) { d[t] = FLT_MAX; ix[t] = 0; }
    float kmax = FLT_MAX;

    for (int c = tid; c < N_CAND; c += T) {
        float v = g_cand_d[c];
        if (v < kmax) {
            bubble_insert(d, ix, v, g_cand_i[c]);
            kmax = d[TOP_K - 1];
        }
    }
    #pragma unroll
    for (int t = 0; t < TOP_K; t++) {
        s_d[tid * TOP_K + t] = d[t];
        s_i[tid * TOP_K + t] = ix[t];
    }
    __syncthreads();

    if (tid < 32) {
        // ---- Stage B: each lane reduces 128 shared entries ----
        #pragma unroll
        for (int t = 0; t < TOP_K; t++) { d[t] = FLT_MAX; ix[t] = 0; }
        kmax = FLT_MAX;
        const int per = (T * TOP_K) / 32;   // 128
        for (int j = 0; j < per; j++) {
            int c = lane * per + j;
            float v = s_d[c];
            if (v < kmax) {
                bubble_insert(d, ix, v, s_i[c]);
                kmax = d[TOP_K - 1];
            }
        }

        // ---- Stage C: 16 extraction rounds over 32 sorted lists ----
        int   ptr    = 0;
        float my_v   = 0.0f;   // lane r keeps round-r winner's psuedo index
        int   my_id  = 0;
        #pragma unroll
        for (int rnd = 0; rnd < TOP_K; rnd++) {
            float bv = (ptr < TOP_K) ? get16f(d, ptr) : FLT_MAX;
            int   bi = (ptr < TOP_K) ? get16i(ix, ptr) : 0;
            int   bl = lane;
            #pragma unroll
            for (int off = 16; off > 0; off >>= 1) {
                float ov = __shfl_xor_sync(0xFFFFFFFFu, bv, off);
                int   oi = __shfl_xor_sync(0xFFFFFFFFu, bi, off);
                int   ol = __shfl_xor_sync(0xFFFFFFFFu, bl, off);
                if (ov < bv || (ov == bv && ol < bl)) { bv = ov; bi = oi; bl = ol; }
            }
            if (lane == bl) ptr++;          // winner advances
            if (lane == rnd) my_id = bi;    // lane rnd records this winner
        }

        // ---- gather + mean ----
        my_v = (lane < TOP_K) ? psuedo[my_id] : 0.0f;
        #pragma unroll
        for (int off = 16; off > 0; off >>= 1)
            my_v += __shfl_xor_sync(0xFFFFFFFFu, my_v, off);
        if (lane == 0) out[0] = my_v * (1.0f / TOP_K);
    }
}

// ---------------------------------------------------------------------------
// Launch. Inputs per metadata order: data_in, transform_mat, ref_data,
// psuedo, K (K hardcoded as TOP_K=16).
// ---------------------------------------------------------------------------
extern "C" void kernel_launch(void* const* d_in, const int* in_sizes, int n_in,
                              void* d_out, int out_size) {
    const float* data_in = (const float*)d_in[0];
    const float* tmat    = (const float*)d_in[1];
    const float* ref     = (const float*)d_in[2];
    const float* psuedo  = (const float*)d_in[3];
    float* out = (float*)d_out;

    project_partial<<<PROJ_BLOCKS, N_PC>>>(data_in, tmat);
    project_reduce<<<1, N_PC>>>();
    dist_topk_kernel<<<BLOCKS, THREADS>>>(ref);
    merge_kernel<<<1, 256>>>(psuedo, out);
}

// round 3
// speedup vs baseline: 9.5192x; 2.3367x over previous
#include <cuda_runtime.h>
#include <float.h>

#define N_REF   500000
#define N_PC    128
#define N_FEAT  2000
#define TOP_K   16

#define BLOCKS           592
#define THREADS          256
#define WARPS_PER_BLOCK  (THREADS / 32)
#define TOTAL_WARPS      (BLOCKS * WARPS_PER_BLOCK)   // 4736
#define N_CAND           (BLOCKS * TOP_K)             // 9472 (block-level top-16)

#define PROJ_BLOCKS      50
#define FEAT_PER_BLOCK   (N_FEAT / PROJ_BLOCKS)       // 40

// Scratch (no cudaMalloc allowed)
__device__ float g_qpart[PROJ_BLOCKS * N_PC];
__device__ float g_query[N_PC];
__device__ float g_cand_d[N_CAND];
__device__ int   g_cand_i[N_CAND];

// ---------------------------------------------------------------------------
// Branch-free register-resident top-16 insert (ascending), pure FSETP/SEL.
// ---------------------------------------------------------------------------
__device__ __forceinline__ void bubble_insert(float (&d)[TOP_K], int (&ix)[TOP_K],
                                              float v, int id) {
    #pragma unroll
    for (int t = 0; t < TOP_K; t++) {
        bool sw  = v < d[t];
        float tv = d[t];
        int   ti = ix[t];
        d[t]  = sw ? v  : tv;
        ix[t] = sw ? id : ti;
        v     = sw ? tv : v;
        id    = sw ? ti : id;
    }
}

// Unrolled dynamic read of small register arrays (SELs, no local memory)
__device__ __forceinline__ float get16f(const float (&a)[TOP_K], int p) {
    float r = a[0];
    #pragma unroll
    for (int t = 1; t < TOP_K; t++) r = (p == t) ? a[t] : r;
    return r;
}
__device__ __forceinline__ int get16i(const int (&a)[TOP_K], int p) {
    int r = a[0];
    #pragma unroll
    for (int t = 1; t < TOP_K; t++) r = (p == t) ? a[t] : r;
    return r;
}
__device__ __forceinline__ float get4f(const float (&a)[4], int p) {
    float r = a[0];
    #pragma unroll
    for (int t = 1; t < 4; t++) r = (p == t) ? a[t] : r;
    return r;
}
__device__ __forceinline__ int get4i(const int (&a)[4], int p) {
    int r = a[0];
    #pragma unroll
    for (int t = 1; t < 4; t++) r = (p == t) ? a[t] : r;
    return r;
}

// ---------------------------------------------------------------------------
// Warp-collective: merge 128 (d,i) entries in shared -> top-16.
// Lane l grabs entries {l, l+32, l+64, l+96}, sorts its 4 in registers
// (5-CAS network), then 16 shuffle-argmin extraction rounds.
// After: lane r (r<16) holds the r-th smallest in (wd, wi).
// ---------------------------------------------------------------------------
__device__ __forceinline__ void warp_merge128(const float* sd, const int* si,
                                              int lane, float& wd, int& wi) {
    float a[4]; int b[4];
    #pragma unroll
    for (int t = 0; t < 4; t++) { a[t] = sd[lane + t * 32]; b[t] = si[lane + t * 32]; }
    // sort-4 network: (0,1)(2,3)(0,2)(1,3)(1,2)
    #define CAS(x, y) { bool sw = a[y] < a[x]; float tf = a[x]; int ti = b[x]; \
                        a[x] = sw ? a[y] : a[x]; b[x] = sw ? b[y] : b[x];      \
                        a[y] = sw ? tf : a[y];   b[y] = sw ? ti : b[y]; }
    CAS(0,1) CAS(2,3) CAS(0,2) CAS(1,3) CAS(1,2)
    #undef CAS

    int ptr = 0;
    wd = FLT_MAX; wi = 0;
    #pragma unroll
    for (int rnd = 0; rnd < TOP_K; rnd++) {
        float bv = (ptr < 4) ? get4f(a, ptr) : FLT_MAX;
        int   bi = (ptr < 4) ? get4i(b, ptr) : 0;
        int   bl = lane;
        #pragma unroll
        for (int off = 16; off > 0; off >>= 1) {
            float ov = __shfl_xor_sync(0xFFFFFFFFu, bv, off);
            int   oi = __shfl_xor_sync(0xFFFFFFFFu, bi, off);
            int   ol = __shfl_xor_sync(0xFFFFFFFFu, bl, off);
            if (ov < bv || (ov == bv && ol < bl)) { bv = ov; bi = oi; bl = ol; }
        }
        if (lane == bl) ptr++;
        if (lane == rnd) { wd = bv; wi = bi; }
    }
}

// ---------------------------------------------------------------------------
// Kernel A1/A2: query projection (split 50 ways, then reduce)
// ---------------------------------------------------------------------------
__global__ void project_partial(const float* __restrict__ data_in,
                                const float* __restrict__ tmat) {
    int j  = threadIdx.x;
    int b  = blockIdx.x;
    int k0 = b * FEAT_PER_BLOCK;
    float acc = 0.0f;
    #pragma unroll 8
    for (int k = k0; k < k0 + FEAT_PER_BLOCK; k++)
        acc += data_in[k] * tmat[k * N_PC + j];
    g_qpart[b * N_PC + j] = acc;
}

__global__ void project_reduce() {
    int j = threadIdx.x;
    float acc = 0.0f;
    #pragma unroll
    for (int b = 0; b < PROJ_BLOCKS; b++) acc += g_qpart[b * N_PC + j];
    g_query[j] = acc;
}

// ---------------------------------------------------------------------------
// Kernel B: streaming L1 distance + per-warp top-16 + BLOCK-level top-16.
// One warp per row; lane l reads a float4 (512B/row coalesced). Unroll 4 rows
// -> MLP=4/lane. At the end, 8 warp lists merge to one block list (cheap,
// parallel across all blocks) -> N_CAND shrinks 8x.
// ---------------------------------------------------------------------------
__global__ void __launch_bounds__(THREADS)
dist_topk_kernel(const float* __restrict__ ref) {
    const int lane = threadIdx.x & 31;
    const int wid  = threadIdx.x >> 5;
    const int gw   = blockIdx.x * WARPS_PER_BLOCK + wid;

    const float4 q = reinterpret_cast<const float4*>(g_query)[lane];

    const int chunk = (N_REF + TOTAL_WARPS - 1) / TOTAL_WARPS;  // 106
    int start = gw * chunk;
    int end   = start + chunk;
    if (start > N_REF) start = N_REF;
    if (end   > N_REF) end   = N_REF;

    float topd[TOP_K];
    int   topi[TOP_K];
    #pragma unroll
    for (int t = 0; t < TOP_K; t++) { topd[t] = FLT_MAX; topi[t] = 0; }
    float kmax = FLT_MAX;

    const float4* __restrict__ ref4 = reinterpret_cast<const float4*>(ref);

    int r = start;
    for (; r + 4 <= end; r += 4) {
        float4 a0 = __ldcs(ref4 + (size_t)(r + 0) * (N_PC / 4) + lane);
        float4 a1 = __ldcs(ref4 + (size_t)(r + 1) * (N_PC / 4) + lane);
        float4 a2 = __ldcs(ref4 + (size_t)(r + 2) * (N_PC / 4) + lane);
        float4 a3 = __ldcs(ref4 + (size_t)(r + 3) * (N_PC / 4) + lane);

        float s0 = fabsf(a0.x - q.x) + fabsf(a0.y - q.y) + fabsf(a0.z - q.z) + fabsf(a0.w - q.w);
        float s1 = fabsf(a1.x - q.x) + fabsf(a1.y - q.y) + fabsf(a1.z - q.z) + fabsf(a1.w - q.w);
        float s2 = fabsf(a2.x - q.x) + fabsf(a2.y - q.y) + fabsf(a2.z - q.z) + fabsf(a2.w - q.w);
        float s3 = fabsf(a3.x - q.x) + fabsf(a3.y - q.y) + fabsf(a3.z - q.z) + fabsf(a3.w - q.w);

        #pragma unroll
        for (int off = 16; off > 0; off >>= 1) {
            s0 += __shfl_xor_sync(0xFFFFFFFFu, s0, off);
            s1 += __shfl_xor_sync(0xFFFFFFFFu, s1, off);
            s2 += __shfl_xor_sync(0xFFFFFFFFu, s2, off);
            s3 += __shfl_xor_sync(0xFFFFFFFFu, s3, off);
        }

        if (lane == 0) {
            if (s0 < kmax) { bubble_insert(topd, topi, s0, r + 0); kmax = topd[TOP_K - 1]; }
            if (s1 < kmax) { bubble_insert(topd, topi, s1, r + 1); kmax = topd[TOP_K - 1]; }
            if (s2 < kmax) { bubble_insert(topd, topi, s2, r + 2); kmax = topd[TOP_K - 1]; }
            if (s3 < kmax) { bubble_insert(topd, topi, s3, r + 3); kmax = topd[TOP_K - 1]; }
        }
    }
    for (; r < end; r++) {
        float4 a0 = __ldcs(ref4 + (size_t)r * (N_PC / 4) + lane);
        float s0 = fabsf(a0.x - q.x) + fabsf(a0.y - q.y) + fabsf(a0.z - q.z) + fabsf(a0.w - q.w);
        #pragma unroll
        for (int off = 16; off > 0; off >>= 1)
            s0 += __shfl_xor_sync(0xFFFFFFFFu, s0, off);
        if (lane == 0 && s0 < kmax) {
            bubble_insert(topd, topi, s0, r);
            kmax = topd[TOP_K - 1];
        }
    }

    // ---- block-level reduction: 8 warp-lists (128 entries) -> block top-16 ----
    __shared__ float sbd[WARPS_PER_BLOCK * TOP_K];   // 128
    __shared__ int   sbi[WARPS_PER_BLOCK * TOP_K];
    if (lane == 0) {
        #pragma unroll
        for (int t = 0; t < TOP_K; t++) {
            sbd[wid * TOP_K + t] = topd[t];
            sbi[wid * TOP_K + t] = topi[t];
        }
    }
    __syncthreads();

    if (wid == 0) {
        float wd; int wi;
        warp_merge128(sbd, sbi, lane, wd, wi);
        if (lane < TOP_K) {
            g_cand_d[blockIdx.x * TOP_K + lane] = wd;
            g_cand_i[blockIdx.x * TOP_K + lane] = wi;
        }
    }
}

// ---------------------------------------------------------------------------
// Kernel C: merge 9472 candidates -> global top-16 -> mean(psuedo[idx]).
// Stage A: 256 threads, 37 cands each, batched loads (MLP~16) -> reg top-16.
// Stage B1: 8 warps each reduce 512 shared entries -> 8 warp top-16s.
// Stage B2: warp 0 merges 128 -> final top-16 -> gather + mean.
// ---------------------------------------------------------------------------
__global__ void merge_kernel(const float* __restrict__ psuedo,
                             float* __restrict__ out) {
    const int T    = 256;
    const int tid  = threadIdx.x;
    const int lane = tid & 31;
    const int wid  = tid >> 5;
    const int CPT  = N_CAND / T;   // 37

    __shared__ float s_d[T * TOP_K];   // 4096
    __shared__ int   s_i[T * TOP_K];
    __shared__ float s_wd[WARPS_PER_BLOCK * TOP_K];  // 128
    __shared__ int   s_wi[WARPS_PER_BLOCK * TOP_K];

    // ---- Stage A: batched, latency-hiding candidate scan ----
    float d[TOP_K]; int ix[TOP_K];
    #pragma unroll
    for (int t = 0; t < TOP_K; t++) { d[t] = FLT_MAX; ix[t] = 0; }
    float kmax = FLT_MAX;

    for (int base = 0; base < CPT; base += 8) {
        float vb[8]; int cb[8];
        #pragma unroll
        for (int j = 0; j < 8; j++) {
            int k = base + j;
            int c = tid + k * T;           // coalesced
            bool ok = (k < CPT);
            vb[j] = ok ? g_cand_d[c] : FLT_MAX;
            cb[j] = ok ? g_cand_i[c] : 0;
        }
        float bmin = vb[0];
        #pragma unroll
        for (int j = 1; j < 8; j++) bmin = fminf(bmin, vb[j]);
        if (bmin < kmax) {
            #pragma unroll
            for (int j = 0; j < 8; j++) {
                if (vb[j] < kmax) {
                    bubble_insert(d, ix, vb[j], cb[j]);
                    kmax = d[TOP_K - 1];
                }
            }
        }
    }
    #pragma unroll
    for (int t = 0; t < TOP_K; t++) {
        s_d[tid * TOP_K + t] = d[t];
        s_i[tid * TOP_K + t] = ix[t];
    }
    __syncthreads();

    // ---- Stage B1: each warp reduces its 512 entries (16/lane) ----
    #pragma unroll
    for (int t = 0; t < TOP_K; t++) { d[t] = FLT_MAX; ix[t] = 0; }
    kmax = FLT_MAX;
    const int wbase = wid * 512;
    #pragma unroll
    for (int t = 0; t < 16; t++) {
        int c = wbase + lane + t * 32;   // conflict-free LDS
        float v = s_d[c];
        if (v < kmax) {
            bubble_insert(d, ix, v, s_i[c]);
            kmax = d[TOP_K - 1];
        }
    }
    // per-warp extraction: 16 rounds over 32 sorted-16 lists
    {
        int ptr = 0;
        float wd = FLT_MAX; int wi = 0;
        #pragma unroll
        for (int rnd = 0; rnd < TOP_K; rnd++) {
            float bv = (ptr < TOP_K) ? get16f(d, ptr) : FLT_MAX;
            int   bi = (ptr < TOP_K) ? get16i(ix, ptr) : 0;
            int   bl = lane;
            #pragma unroll
            for (int off = 16; off > 0; off >>= 1) {
                float ov = __shfl_xor_sync(0xFFFFFFFFu, bv, off);
                int   oi = __shfl_xor_sync(0xFFFFFFFFu, bi, off);
                int   ol = __shfl_xor_sync(0xFFFFFFFFu, bl, off);
                if (ov < bv || (ov == bv && ol < bl)) { bv = ov; bi = oi; bl = ol; }
            }
            if (lane == bl) ptr++;
            if (lane == rnd) { wd = bv; wi = bi; }
        }
        if (lane < TOP_K) {
            s_wd[wid * TOP_K + lane] = wd;
            s_wi[wid * TOP_K + lane] = wi;
        }
    }
    __syncthreads();

    // ---- Stage B2: warp 0 merges 128 -> final 16, gather + mean ----
    if (wid == 0) {
        float wd; int wi;
        warp_merge128(s_wd, s_wi, lane, wd, wi);
        float v = (lane < TOP_K) ? psuedo[wi] : 0.0f;
        #pragma unroll
        for (int off = 16; off > 0; off >>= 1)
            v += __shfl_xor_sync(0xFFFFFFFFu, v, off);
        if (lane == 0) out[0] = v * (1.0f / TOP_K);
    }
}

// ---------------------------------------------------------------------------
// Launch
// ---------------------------------------------------------------------------
extern "C" void kernel_launch(void* const* d_in, const int* in_sizes, int n_in,
                              void* d_out, int out_size) {
    const float* data_in = (const float*)d_in[0];
    const float* tmat    = (const float*)d_in[1];
    const float* ref     = (const float*)d_in[2];
    const float* psuedo  = (const float*)d_in[3];
    float* out = (float*)d_out;

    project_partial<<<PROJ_BLOCKS, N_PC>>>(data_in, tmat);
    project_reduce<<<1, N_PC>>>();
    dist_topk_kernel<<<BLOCKS, THREADS>>>(ref);
    merge_kernel<<<1, 256>>>(psuedo, out);
}

// round 4
// speedup vs baseline: 10.5114x; 1.1042x over previous
#include <cuda_runtime.h>
#include <float.h>

#define N_REF   500000
#define N_PC    128
#define N_FEAT  2000
#define TOP_K   16

#define BLOCKS           592
#define THREADS          256
#define WARPS_PER_BLOCK  (THREADS / 32)
#define TOTAL_WARPS      (BLOCKS * WARPS_PER_BLOCK)   // 4736
#define N_CAND           (BLOCKS * TOP_K)             // 9472
#define M1_BLOCKS        37                           // 37*256 = 9472 exactly
#define N_CAND2          (M1_BLOCKS * TOP_K)          // 592

#define PROJ_BLOCKS      50
#define FEAT_PER_BLOCK   (N_FEAT / PROJ_BLOCKS)       // 40

// Scratch (no cudaMalloc allowed)
__device__ float g_qpart[PROJ_BLOCKS * N_PC];
__device__ float g_query[N_PC];
__device__ float g_cand_d[N_CAND];
__device__ int   g_cand_i[N_CAND];
__device__ float g_cand2_d[N_CAND2];
__device__ int   g_cand2_i[N_CAND2];

// ---------------------------------------------------------------------------
// Branch-free register top-16 insert (used ONLY inside the streaming dist
// kernel at lane 0, where it's rare and hidden behind DRAM latency).
// ---------------------------------------------------------------------------
__device__ __forceinline__ void bubble_insert(float (&d)[TOP_K], int (&ix)[TOP_K],
                                              float v, int id) {
    #pragma unroll
    for (int t = 0; t < TOP_K; t++) {
        bool sw  = v < d[t];
        float tv = d[t];
        int   ti = ix[t];
        d[t]  = sw ? v  : tv;
        ix[t] = sw ? id : ti;
        v     = sw ? tv : v;
        id    = sw ? ti : id;
    }
}

// Unrolled dynamic reads of small register arrays (SELs, no local memory)
__device__ __forceinline__ float get4f(const float (&a)[4], int p) {
    float r = a[0];
    #pragma unroll
    for (int t = 1; t < 4; t++) r = (p == t) ? a[t] : r;
    return r;
}
__device__ __forceinline__ int get4i(const int (&a)[4], int p) {
    int r = a[0];
    #pragma unroll
    for (int t = 1; t < 4; t++) r = (p == t) ? a[t] : r;
    return r;
}
__device__ __forceinline__ float get3f(const float (&a)[3], int p) {
    float r = a[0];
    r = (p == 1) ? a[1] : r;
    r = (p == 2) ? a[2] : r;
    return r;
}
__device__ __forceinline__ int get3i(const int (&a)[3], int p) {
    int r = a[0];
    r = (p == 1) ? a[1] : r;
    r = (p == 2) ? a[2] : r;
    return r;
}

// ---------------------------------------------------------------------------
// Full bitonic sort of 32 (v,i) pairs across a warp (ascending by lane).
// 15 shuffle stages, zero serial insert chains.
// ---------------------------------------------------------------------------
__device__ __forceinline__ void bitonic32(float& v, int& i, int lane) {
    #pragma unroll
    for (int k = 2; k <= 32; k <<= 1) {
        #pragma unroll
        for (int j = k >> 1; j > 0; j >>= 1) {
            float ov = __shfl_xor_sync(0xFFFFFFFFu, v, j);
            int   oi = __shfl_xor_sync(0xFFFFFFFFu, i, j);
            bool up      = ((lane & k) == 0);
            bool lower   = ((lane & j) == 0);
            bool takeMin = (lower == up);
            bool sel = takeMin ? (ov < v) : (ov > v);
            v = sel ? ov : v;
            i = sel ? oi : i;
        }
    }
}

// ---------------------------------------------------------------------------
// Warp-collective: 128 (d,i) entries in shared -> sorted top-16 at lanes 0-15.
// ---------------------------------------------------------------------------
__device__ __forceinline__ void warp_merge128(const float* sd, const int* si,
                                              int lane, float& wd, int& wi) {
    float a[4]; int b[4];
    #pragma unroll
    for (int t = 0; t < 4; t++) { a[t] = sd[lane + t * 32]; b[t] = si[lane + t * 32]; }
    #define CAS(x, y) { bool sw = a[y] < a[x]; float tf = a[x]; int ti = b[x]; \
                        a[x] = sw ? a[y] : a[x]; b[x] = sw ? b[y] : b[x];      \
                        a[y] = sw ? tf : a[y];   b[y] = sw ? ti : b[y]; }
    CAS(0,1) CAS(2,3) CAS(0,2) CAS(1,3) CAS(1,2)
    #undef CAS

    int ptr = 0;
    wd = FLT_MAX; wi = 0;
    #pragma unroll
    for (int rnd = 0; rnd < TOP_K; rnd++) {
        float bv = (ptr < 4) ? get4f(a, ptr) : FLT_MAX;
        int   bi = (ptr < 4) ? get4i(b, ptr) : 0;
        int   bl = lane;
        #pragma unroll
        for (int off = 16; off > 0; off >>= 1) {
            float ov = __shfl_xor_sync(0xFFFFFFFFu, bv, off);
            int   oi = __shfl_xor_sync(0xFFFFFFFFu, bi, off);
            int   ol = __shfl_xor_sync(0xFFFFFFFFu, bl, off);
            if (ov < bv || (ov == bv && ol < bl)) { bv = ov; bi = oi; bl = ol; }
        }
        if (lane == bl) ptr++;
        if (lane == rnd) { wd = bv; wi = bi; }
    }
}

// ---------------------------------------------------------------------------
// Kernel A1/A2: query projection
// ---------------------------------------------------------------------------
__global__ void project_partial(const float* __restrict__ data_in,
                                const float* __restrict__ tmat) {
    int j  = threadIdx.x;
    int b  = blockIdx.x;
    int k0 = b * FEAT_PER_BLOCK;
    float acc = 0.0f;
    #pragma unroll 8
    for (int k = k0; k < k0 + FEAT_PER_BLOCK; k++)
        acc += data_in[k] * tmat[k * N_PC + j];
    g_qpart[b * N_PC + j] = acc;
}

__global__ void project_reduce() {
    int j = threadIdx.x;
    float acc = 0.0f;
    #pragma unroll
    for (int b = 0; b < PROJ_BLOCKS; b++) acc += g_qpart[b * N_PC + j];
    g_query[j] = acc;
}

// ---------------------------------------------------------------------------
// Kernel B: streaming L1 distance + per-warp top-16 + block top-16.
// ---------------------------------------------------------------------------
__global__ void __launch_bounds__(THREADS)
dist_topk_kernel(const float* __restrict__ ref) {
    const int lane = threadIdx.x & 31;
    const int wid  = threadIdx.x >> 5;
    const int gw   = blockIdx.x * WARPS_PER_BLOCK + wid;

    const float4 q = reinterpret_cast<const float4*>(g_query)[lane];

    const int chunk = (N_REF + TOTAL_WARPS - 1) / TOTAL_WARPS;  // 106
    int start = gw * chunk;
    int end   = start + chunk;
    if (start > N_REF) start = N_REF;
    if (end   > N_REF) end   = N_REF;

    float topd[TOP_K];
    int   topi[TOP_K];
    #pragma unroll
    for (int t = 0; t < TOP_K; t++) { topd[t] = FLT_MAX; topi[t] = 0; }
    float kmax = FLT_MAX;

    const float4* __restrict__ ref4 = reinterpret_cast<const float4*>(ref);

    int r = start;
    for (; r + 4 <= end; r += 4) {
        float4 a0 = __ldcs(ref4 + (size_t)(r + 0) * (N_PC / 4) + lane);
        float4 a1 = __ldcs(ref4 + (size_t)(r + 1) * (N_PC / 4) + lane);
        float4 a2 = __ldcs(ref4 + (size_t)(r + 2) * (N_PC / 4) + lane);
        float4 a3 = __ldcs(ref4 + (size_t)(r + 3) * (N_PC / 4) + lane);

        float s0 = fabsf(a0.x - q.x) + fabsf(a0.y - q.y) + fabsf(a0.z - q.z) + fabsf(a0.w - q.w);
        float s1 = fabsf(a1.x - q.x) + fabsf(a1.y - q.y) + fabsf(a1.z - q.z) + fabsf(a1.w - q.w);
        float s2 = fabsf(a2.x - q.x) + fabsf(a2.y - q.y) + fabsf(a2.z - q.z) + fabsf(a2.w - q.w);
        float s3 = fabsf(a3.x - q.x) + fabsf(a3.y - q.y) + fabsf(a3.z - q.z) + fabsf(a3.w - q.w);

        #pragma unroll
        for (int off = 16; off > 0; off >>= 1) {
            s0 += __shfl_xor_sync(0xFFFFFFFFu, s0, off);
            s1 += __shfl_xor_sync(0xFFFFFFFFu, s1, off);
            s2 += __shfl_xor_sync(0xFFFFFFFFu, s2, off);
            s3 += __shfl_xor_sync(0xFFFFFFFFu, s3, off);
        }

        if (lane == 0) {
            if (s0 < kmax) { bubble_insert(topd, topi, s0, r + 0); kmax = topd[TOP_K - 1]; }
            if (s1 < kmax) { bubble_insert(topd, topi, s1, r + 1); kmax = topd[TOP_K - 1]; }
            if (s2 < kmax) { bubble_insert(topd, topi, s2, r + 2); kmax = topd[TOP_K - 1]; }
            if (s3 < kmax) { bubble_insert(topd, topi, s3, r + 3); kmax = topd[TOP_K - 1]; }
        }
    }
    for (; r < end; r++) {
        float4 a0 = __ldcs(ref4 + (size_t)r * (N_PC / 4) + lane);
        float s0 = fabsf(a0.x - q.x) + fabsf(a0.y - q.y) + fabsf(a0.z - q.z) + fabsf(a0.w - q.w);
        #pragma unroll
        for (int off = 16; off > 0; off >>= 1)
            s0 += __shfl_xor_sync(0xFFFFFFFFu, s0, off);
        if (lane == 0 && s0 < kmax) {
            bubble_insert(topd, topi, s0, r);
            kmax = topd[TOP_K - 1];
        }
    }

    __shared__ float sbd[WARPS_PER_BLOCK * TOP_K];   // 128
    __shared__ int   sbi[WARPS_PER_BLOCK * TOP_K];
    if (lane == 0) {
        #pragma unroll
        for (int t = 0; t < TOP_K; t++) {
            sbd[wid * TOP_K + t] = topd[t];
            sbi[wid * TOP_K + t] = topi[t];
        }
    }
    __syncthreads();

    if (wid == 0) {
        float wd; int wi;
        warp_merge128(sbd, sbi, lane, wd, wi);
        if (lane < TOP_K) {
            g_cand_d[blockIdx.x * TOP_K + lane] = wd;
            g_cand_i[blockIdx.x * TOP_K + lane] = wi;
        }
    }
}

// ---------------------------------------------------------------------------
// Kernel C1: 37 blocks x 256 threads; 1 candidate per thread.
// warp bitonic sort-32 -> top-16/warp -> 128 shared -> block top-16.
// 9472 -> 592 candidates, fully parallel, no insert chains.
// ---------------------------------------------------------------------------
__global__ void merge1_kernel() {
    const int tid  = threadIdx.x;
    const int lane = tid & 31;
    const int wid  = tid >> 5;

    int c = blockIdx.x * 256 + tid;           // 37*256 == N_CAND exactly
    float v = g_cand_d[c];
    int   id = g_cand_i[c];

    bitonic32(v, id, lane);

    __shared__ float sd[WARPS_PER_BLOCK * TOP_K];
    __shared__ int   si[WARPS_PER_BLOCK * TOP_K];
    if (lane < TOP_K) {
        sd[wid * TOP_K + lane] = v;
        si[wid * TOP_K + lane] = id;
    }
    __syncthreads();

    if (wid == 0) {
        float wd; int wi;
        warp_merge128(sd, si, lane, wd, wi);
        if (lane < TOP_K) {
            g_cand2_d[blockIdx.x * TOP_K + lane] = wd;
            g_cand2_i[blockIdx.x * TOP_K + lane] = wi;
        }
    }
}

// ---------------------------------------------------------------------------
// Kernel C2: 1 block x 256 threads; 592 candidates (<=3 per thread, sort-3).
// per-warp 16-round extraction over 96 values -> 128 shared -> final 16 ->
// gather psuedo -> mean.
// ---------------------------------------------------------------------------
__global__ void merge2_kernel(const float* __restrict__ psuedo,
                              float* __restrict__ out) {
    const int tid  = threadIdx.x;
    const int lane = tid & 31;
    const int wid  = tid >> 5;

    float a[3]; int b[3];
    #pragma unroll
    for (int t = 0; t < 3; t++) {
        int c = tid + t * 256;
        bool ok = (c < N_CAND2);
        a[t] = ok ? g_cand2_d[c] : FLT_MAX;
        b[t] = ok ? g_cand2_i[c] : 0;
    }
    // sort-3
    #define CAS3(x, y) { bool sw = a[y] < a[x]; float tf = a[x]; int ti = b[x]; \
                         a[x] = sw ? a[y] : a[x]; b[x] = sw ? b[y] : b[x];      \
                         a[y] = sw ? tf : a[y];   b[y] = sw ? ti : b[y]; }
    CAS3(0,1) CAS3(1,2) CAS3(0,1)
    #undef CAS3

    // per-warp extraction: top-16 of 32 sorted-3 lists
    __shared__ float s_wd[WARPS_PER_BLOCK * TOP_K];
    __shared__ int   s_wi[WARPS_PER_BLOCK * TOP_K];
    {
        int ptr = 0;
        float wd = FLT_MAX; int wi = 0;
        #pragma unroll
        for (int rnd = 0; rnd < TOP_K; rnd++) {
            float bv = (ptr < 3) ? get3f(a, ptr) : FLT_MAX;
            int   bi = (ptr < 3) ? get3i(b, ptr) : 0;
            int   bl = lane;
            #pragma unroll
            for (int off = 16; off > 0; off >>= 1) {
                float ov = __shfl_xor_sync(0xFFFFFFFFu, bv, off);
                int   oi = __shfl_xor_sync(0xFFFFFFFFu, bi, off);
                int   ol = __shfl_xor_sync(0xFFFFFFFFu, bl, off);
                if (ov < bv || (ov == bv && ol < bl)) { bv = ov; bi = oi; bl = ol; }
            }
            if (lane == bl) ptr++;
            if (lane == rnd) { wd = bv; wi = bi; }
        }
        if (lane < TOP_K) {
            s_wd[wid * TOP_K + lane] = wd;
            s_wi[wid * TOP_K + lane] = wi;
        }
    }
    __syncthreads();

    if (wid == 0) {
        float wd; int wi;
        warp_merge128(s_wd, s_wi, lane, wd, wi);
        float v = (lane < TOP_K) ? psuedo[wi] : 0.0f;
        #pragma unroll
        for (int off = 16; off > 0; off >>= 1)
            v += __shfl_xor_sync(0xFFFFFFFFu, v, off);
        if (lane == 0) out[0] = v * (1.0f / TOP_K);
    }
}

// ---------------------------------------------------------------------------
// Launch
// ---------------------------------------------------------------------------
extern "C" void kernel_launch(void* const* d_in, const int* in_sizes, int n_in,
                              void* d_out, int out_size) {
    const float* data_in = (const float*)d_in[0];
    const float* tmat    = (const float*)d_in[1];
    const float* ref     = (const float*)d_in[2];
    const float* psuedo  = (const float*)d_in[3];
    float* out = (float*)d_out;

    project_partial<<<PROJ_BLOCKS, N_PC>>>(data_in, tmat);
    project_reduce<<<1, N_PC>>>();
    dist_topk_kernel<<<BLOCKS, THREADS>>>(ref);
    merge1_kernel<<<M1_BLOCKS, 256>>>();
    merge2_kernel<<<1, 256>>>(psuedo, out);
}